// round 11
// baseline (speedup 1.0000x reference)
#include <cuda_runtime.h>
#include <cstdint>

// Problem constants
#define NPTS   131072
#define DIMK   64
#define KCENT  1024
#define INROW  128

#define THREADS 256          // 8 warps; each warp owns 16 points
#define BM      128          // points per CTA
#define NTILES  (KCENT / 8)  // 128 n8-tiles
#define TPC     8            // tiles per chunk (64 centers)
#define NCHUNK  (NTILES / TPC)          // 16
#define CHUNK_BYTES (TPC * 8 * 32 * 8)  // 16384 (hi-only fragments)
#define CN_OFF  (2 * CHUNK_BYTES)       // after the two chunk buffers
#define SMEM_REQ (CN_OFF + KCENT * 4)   // 36864

__device__ float g_cnorm[KCENT];
__device__ int   g_chimax_bits;   // max_n ||c_hi,n||  (float bits, monotone)
__device__ int   g_clomax_bits;   // max_n ||c_lo,n||
__device__ int   g_flagcnt;
__device__ int   g_flaglist[NPTS];
// B hi-fragments, tile-major: [tile(128)][kstep(8)][lane(32)] x uint2
// uint2 = tf32 hi bits of centers[n][k], centers[n][k+4],
// n = tile*8 + lane/4, k = kstep*8 + lane%4.
__device__ __align__(16) uint2 g_bfrag[NTILES * 8 * 32];

// ---------------- helpers ----------------
__device__ __forceinline__ unsigned to_tf32(float x) {
    unsigned u;
    asm("cvt.rna.tf32.f32 %0, %1;" : "=r"(u) : "f"(x));
    return u;
}
__device__ __forceinline__ void mma_tf32(float d[4], const unsigned a[4],
                                         unsigned b0, unsigned b1) {
    asm("mma.sync.aligned.m16n8k8.row.col.f32.tf32.tf32.f32 "
        "{%0,%1,%2,%3}, {%4,%5,%6,%7}, {%8,%9}, {%0,%1,%2,%3};"
        : "+f"(d[0]), "+f"(d[1]), "+f"(d[2]), "+f"(d[3])
        : "r"(a[0]), "r"(a[1]), "r"(a[2]), "r"(a[3]), "r"(b0), "r"(b1));
}
__device__ __forceinline__ void cp_async16(unsigned smem_addr, const void* g) {
    asm volatile("cp.async.cg.shared.global [%0], [%1], 16;"
                 :: "r"(smem_addr), "l"(g));
}

// ---------------- prep: norms, split-norm maxima, counter reset ----------------
__global__ void cnorm_kernel(const float* __restrict__ centers) {
    int n = blockIdx.x * blockDim.x + threadIdx.x;
    if (n == 0) g_flagcnt = 0;           // reset per replay (before pass 1)
    if (n < KCENT) {
        const float4* c = reinterpret_cast<const float4*>(
            centers + (size_t)n * DIMK);
        float s0 = 0.f, s1 = 0.f, s2 = 0.f, s3 = 0.f;
        float shi = 0.f, slo = 0.f;
        #pragma unroll
        for (int k = 0; k < DIMK / 4; k++) {
            float4 v = __ldg(c + k);
            s0 = fmaf(v.x, v.x, s0);
            s1 = fmaf(v.y, v.y, s1);
            s2 = fmaf(v.z, v.z, s2);
            s3 = fmaf(v.w, v.w, s3);
            float e[4] = {v.x, v.y, v.z, v.w};
            #pragma unroll
            for (int j = 0; j < 4; j++) {
                float h = __uint_as_float(to_tf32(e[j]));
                float l = e[j] - h;       // exact
                shi = fmaf(h, h, shi);
                slo = fmaf(l, l, slo);
            }
        }
        g_cnorm[n] = (s0 + s1) + (s2 + s3);
        // maxima (positive floats: int-bit compare is order-preserving)
        atomicMax(&g_chimax_bits, __float_as_int(sqrtf(shi) * 1.0001f));
        atomicMax(&g_clomax_bits, __float_as_int(sqrtf(slo) * 1.0001f));
    }
}

// Build fragment-ordered tf32 hi blob from centers.
__global__ void csplit_kernel(const float* __restrict__ centers) {
    int id = blockIdx.x * blockDim.x + threadIdx.x;   // 128*8*32 = 32768
    if (id >= NTILES * 8 * 32) return;
    int lane = id & 31;
    int q    = (id >> 5) & 7;
    int t    = id >> 8;
    int n = t * 8 + (lane >> 2);
    int k = q * 8 + (lane & 3);
    unsigned h0 = to_tf32(__ldg(centers + (size_t)n * DIMK + k));
    unsigned h1 = to_tf32(__ldg(centers + (size_t)n * DIMK + k + 4));
    g_bfrag[(t * 8 + q) * 32 + lane] = make_uint2(h0, h1);
}

// ---------------- pass 1: hh-only tf32 GEMM + two-smallest + flag ----------------
__global__ void __launch_bounds__(THREADS)
label_mma_kernel(const float* __restrict__ inpt, float* __restrict__ out) {
    extern __shared__ __align__(16) unsigned char sm[];
    const unsigned sbase = (unsigned)__cvta_generic_to_shared(sm);
    float* cn_s = reinterpret_cast<float*>(sm + CN_OFF);

    const int tid  = threadIdx.x;
    const int wid  = tid >> 5;
    const int lane = tid & 31;
    const int r    = lane >> 2;   // 0..7
    const int cc   = lane & 3;    // 0..3
    const int m0   = blockIdx.x * BM;
    const int mrow = m0 + wid * 16;

    // Prefetch chunk 0 (linear copy: blob layout == smem layout)
    {
        const unsigned char* src = (const unsigned char*)g_bfrag;
        #pragma unroll
        for (int j = 0; j < CHUNK_BYTES / (THREADS * 16); j++)
            cp_async16(sbase + tid * 16 + j * (THREADS * 16),
                       src + tid * 16 + j * (THREADS * 16));
        asm volatile("cp.async.commit_group;");
    }

    // Center norms -> smem
    for (int i = tid; i < KCENT; i += THREADS) cn_s[i] = g_cnorm[i];

    // A hi-fragments + per-row split-norm partial sums
    unsigned ahi[8][4];
    float sxh0 = 0.f, sxl0 = 0.f, sxh1 = 0.f, sxl1 = 0.f;
    {
        const float* row0 = inpt + (size_t)(mrow + r) * INROW + DIMK;
        const float* row8 = inpt + (size_t)(mrow + r + 8) * INROW + DIMK;
        #pragma unroll
        for (int q = 0; q < 8; q++) {
            float x0 = __ldg(row0 + q * 8 + cc);
            float x1 = __ldg(row8 + q * 8 + cc);
            float x2 = __ldg(row0 + q * 8 + cc + 4);
            float x3 = __ldg(row8 + q * 8 + cc + 4);
            ahi[q][0] = to_tf32(x0);
            ahi[q][1] = to_tf32(x1);
            ahi[q][2] = to_tf32(x2);
            ahi[q][3] = to_tf32(x3);
            float h, l;
            h = __uint_as_float(ahi[q][0]); l = x0 - h;
            sxh0 = fmaf(h, h, sxh0); sxl0 = fmaf(l, l, sxl0);
            h = __uint_as_float(ahi[q][1]); l = x1 - h;
            sxh1 = fmaf(h, h, sxh1); sxl1 = fmaf(l, l, sxl1);
            h = __uint_as_float(ahi[q][2]); l = x2 - h;
            sxh0 = fmaf(h, h, sxh0); sxl0 = fmaf(l, l, sxl0);
            h = __uint_as_float(ahi[q][3]); l = x3 - h;
            sxh1 = fmaf(h, h, sxh1); sxl1 = fmaf(l, l, sxl1);
        }
        // reduce across the 4 cc-lanes of each row
        #pragma unroll
        for (int off = 1; off <= 2; off <<= 1) {
            sxh0 += __shfl_xor_sync(0xffffffffu, sxh0, off);
            sxl0 += __shfl_xor_sync(0xffffffffu, sxl0, off);
            sxh1 += __shfl_xor_sync(0xffffffffu, sxh1, off);
            sxl1 += __shfl_xor_sync(0xffffffffu, sxl1, off);
        }
    }

    // Two-smallest tracking per row (m2 label not needed: pass 2 rescans)
    const float INF = __int_as_float(0x7f800000);
    float bd0 = INF, b2d0 = INF, bd1 = INF, b2d1 = INF;
    int   bn0 = 0, bn1 = 0;

    #pragma unroll 1
    for (int c = 0; c < NCHUNK; c++) {
        asm volatile("cp.async.wait_group 0;" ::: "memory");
        __syncthreads();

        if (c + 1 < NCHUNK) {
            const unsigned char* src =
                (const unsigned char*)g_bfrag + (size_t)(c + 1) * CHUNK_BYTES;
            unsigned dst = sbase + ((c + 1) & 1) * CHUNK_BYTES;
            #pragma unroll
            for (int j = 0; j < CHUNK_BYTES / (THREADS * 16); j++)
                cp_async16(dst + tid * 16 + j * (THREADS * 16),
                           src + tid * 16 + j * (THREADS * 16));
            asm volatile("cp.async.commit_group;");
        }

        const unsigned buf = sbase + (c & 1) * CHUNK_BYTES + lane * 8;

        #pragma unroll
        for (int t8 = 0; t8 < TPC; t8 += 2) {    // 2 tiles in flight (ILP)
            float dA[4] = {0.f, 0.f, 0.f, 0.f};
            float dB[4] = {0.f, 0.f, 0.f, 0.f};
            #pragma unroll
            for (int q = 0; q < 8; q++) {
                uint2 ba, bb;
                asm volatile("ld.shared.v2.b32 {%0,%1}, [%2];"
                             : "=r"(ba.x), "=r"(ba.y)
                             : "r"(buf + (((t8 + 0) * 8 + q) * 32) * 8));
                asm volatile("ld.shared.v2.b32 {%0,%1}, [%2];"
                             : "=r"(bb.x), "=r"(bb.y)
                             : "r"(buf + (((t8 + 1) * 8 + q) * 32) * 8));
                mma_tf32(dA, ahi[q], ba.x, ba.y);
                mma_tf32(dB, ahi[q], bb.x, bb.y);
            }
            #pragma unroll
            for (int p = 0; p < 2; p++) {
                const float* d = p ? dB : dA;
                const int nbase = c * 64 + (t8 + p) * 8 + 2 * cc;
                float2 cn = *reinterpret_cast<const float2*>(cn_s + nbase);
                float e0 = fmaf(-2.f, d[0], cn.x);
                float e1 = fmaf(-2.f, d[1], cn.y);
                float e2 = fmaf(-2.f, d[2], cn.x);
                float e3 = fmaf(-2.f, d[3], cn.y);
                // ascending n; two-smallest update
                if (e0 < bd0) { b2d0 = bd0; bd0 = e0; bn0 = nbase; }
                else if (e0 < b2d0) b2d0 = e0;
                if (e1 < bd0) { b2d0 = bd0; bd0 = e1; bn0 = nbase + 1; }
                else if (e1 < b2d0) b2d0 = e1;
                if (e2 < bd1) { b2d1 = bd1; bd1 = e2; bn1 = nbase; }
                else if (e2 < b2d1) b2d1 = e2;
                if (e3 < bd1) { b2d1 = bd1; bd1 = e3; bn1 = nbase + 1; }
                else if (e3 < b2d1) b2d1 = e3;
            }
        }
    }

    // Merge (min, min2) across the 4 cc-lanes (disjoint n-sets)
    #pragma unroll
    for (int off = 1; off <= 2; off <<= 1) {
        float od0 = __shfl_xor_sync(0xffffffffu, bd0, off);
        float o2d0 = __shfl_xor_sync(0xffffffffu, b2d0, off);
        int   on0 = __shfl_xor_sync(0xffffffffu, bn0, off);
        float od1 = __shfl_xor_sync(0xffffffffu, bd1, off);
        float o2d1 = __shfl_xor_sync(0xffffffffu, b2d1, off);
        int   on1 = __shfl_xor_sync(0xffffffffu, bn1, off);
        if (od0 < bd0 || (od0 == bd0 && on0 < bn0)) {
            b2d0 = fminf(bd0, o2d0); bd0 = od0; bn0 = on0;
        } else b2d0 = fminf(b2d0, od0);
        if (od1 < bd1 || (od1 == bd1 && on1 < bn1)) {
            b2d1 = fminf(bd1, o2d1); bd1 = od1; bn1 = on1;
        } else b2d1 = fminf(b2d1, od1);
    }

    if (cc == 0) {
        const float CHI = __int_as_float(g_chimax_bits);
        const float CLO = __int_as_float(g_clomax_bits);
        float nh0 = sqrtf(sxh0), nl0 = sqrtf(sxl0);
        float nh1 = sqrtf(sxh1), nl1 = sqrtf(sxl1);
        // sound per-row error bound on approx distance (see derivation)
        float eps0 = 2.f * (nh0 * CLO + nl0 * (CHI + CLO))
                   + 2e-5f * nh0 * CHI + 1e-3f;
        float eps1 = 2.f * (nh1 * CLO + nl1 * (CHI + CLO))
                   + 2e-5f * nh1 * CHI + 1e-3f;
        out[mrow + r] = (float)bn0;
        out[mrow + r + 8] = (float)bn1;
        if (b2d0 - bd0 <= 2.f * eps0) {
            int i = atomicAdd(&g_flagcnt, 1);
            g_flaglist[i] = mrow + r;
        }
        if (b2d1 - bd1 <= 2.f * eps1) {
            int i = atomicAdd(&g_flagcnt, 1);
            g_flaglist[i] = mrow + r + 8;
        }
    }
}

// ---------------- pass 2: exact fp32 rescan for flagged points ----------------
// One warp per flagged point; lane l covers centers [l*32, l*32+32) (ascending).
__global__ void __launch_bounds__(256)
exact_pass_kernel(const float* __restrict__ inpt,
                  const float* __restrict__ centers,
                  float* __restrict__ out) {
    const int lane = threadIdx.x & 31;
    const int gw   = (blockIdx.x * blockDim.x + threadIdx.x) >> 5;
    const int nw   = (gridDim.x * blockDim.x) >> 5;
    const int cnt  = g_flagcnt;

    for (int i = gw; i < cnt; i += nw) {
        const int m = g_flaglist[i];
        const float4* xr = reinterpret_cast<const float4*>(
            inpt + (size_t)m * INROW + DIMK);
        float4 xv[16];
        #pragma unroll
        for (int j = 0; j < 16; j++) xv[j] = __ldg(xr + j);

        float bm = __int_as_float(0x7f800000);
        int   bn = 0;
        const int nbase = lane * 32;
        for (int c = 0; c < 32; c++) {
            const int n = nbase + c;
            const float4* cr = reinterpret_cast<const float4*>(
                centers + (size_t)n * DIMK);
            float s = 0.f;
            #pragma unroll
            for (int j = 0; j < 16; j++) {
                float4 cv = __ldg(cr + j);
                s = fmaf(xv[j].x, cv.x, s);
                s = fmaf(xv[j].y, cv.y, s);
                s = fmaf(xv[j].z, cv.z, s);
                s = fmaf(xv[j].w, cv.w, s);
            }
            float d = fmaf(-2.f, s, g_cnorm[n]);
            if (d < bm) { bm = d; bn = n; }   // ascending n: first-min
        }
        #pragma unroll
        for (int off = 16; off > 0; off >>= 1) {
            float od = __shfl_down_sync(0xffffffffu, bm, off);
            int   on = __shfl_down_sync(0xffffffffu, bn, off);
            if (od < bm || (od == bm && on < bn)) { bm = od; bn = on; }
        }
        if (lane == 0) out[m] = (float)bn;
    }
}

extern "C" void kernel_launch(void* const* d_in, const int* in_sizes, int n_in,
                              void* d_out, int out_size) {
    // Identify inputs by element count:
    //   inpt: 16777216 elements (unique); centers1: second 65536-elem tensor
    const float* inpt     = nullptr;
    const float* centers1 = nullptr;
    int centers_seen = 0;
    for (int i = 0; i < n_in; i++) {
        if (in_sizes[i] == NPTS * INROW) {
            inpt = (const float*)d_in[i];
        } else if (in_sizes[i] == KCENT * DIMK) {
            centers_seen++;
            if (centers_seen == 2) centers1 = (const float*)d_in[i];
        }
    }
    if (!inpt)     inpt     = (const float*)d_in[0];
    if (!centers1) centers1 = (const float*)d_in[n_in - 1];

    float* out = (float*)d_out;

    cudaFuncSetAttribute(label_mma_kernel,
                         cudaFuncAttributeMaxDynamicSharedMemorySize, SMEM_REQ);

    cnorm_kernel<<<(KCENT + 255) / 256, 256>>>(centers1);
    csplit_kernel<<<(NTILES * 8 * 32 + 255) / 256, 256>>>(centers1);
    label_mma_kernel<<<NPTS / BM, THREADS, SMEM_REQ>>>(inpt, out);
    exact_pass_kernel<<<2048, 256>>>(inpt, centers1, out);
}

// round 12
// speedup vs baseline: 1.8467x; 1.8467x over previous
#include <cuda_runtime.h>
#include <cuda_bf16.h>
#include <cstdint>

// Problem constants
#define NPTS   131072
#define DIMK   64
#define KCENT  1024
#define INROW  128

#define THREADS 256          // 8 warps; each warp owns 16 points
#define BM      128          // points per CTA
#define NTILES  (KCENT / 8)  // 128 n8-tiles
#define TPC     8            // tiles per chunk (64 centers)
#define NCHUNK  (NTILES / TPC)           // 16
#define CHUNK_BYTES (TPC * 4 * 32 * 16)  // 16384 (4 k16-steps, uint4/lane)
#define CN_OFF  (2 * CHUNK_BYTES)        // after the two chunk buffers
#define SMEM_REQ (CN_OFF + KCENT * 4)    // 36864

__device__ float g_cnorm[KCENT];
__device__ int   g_cmax_bits;    // max ||c||        (float bits, monotone)
__device__ int   g_ch1max_bits;  // max ||c_h1||
__device__ int   g_crmax_bits;   // max ||c_resid||
__device__ int   g_flagcnt;
__device__ int   g_flaglist[NPTS];
// B fragments: [tile(128)][q(4 k16-steps)][lane(32)] x uint4
//   n = tile*8 + lane/4, kb = q*16 + 2*(lane%4)
//   .x = bf16x2 h0(c[n][kb]),   h0(c[n][kb+1])      (b0 of h0)
//   .y = bf16x2 h0(c[n][kb+8]), h0(c[n][kb+9])      (b1 of h0)
//   .z / .w = same for h1
__device__ __align__(16) uint4 g_bfrag[NTILES * 4 * 32];

// ---------------- helpers ----------------
__device__ __forceinline__ unsigned pack_bf16(float a, float b) {
    __nv_bfloat162 t = __floats2bfloat162_rn(a, b);   // .x=a (low), .y=b
    return *reinterpret_cast<unsigned*>(&t);
}
__device__ __forceinline__ void split2(float x, float& f0, float& f1, float& r) {
    f0 = __bfloat162float(__float2bfloat16_rn(x));
    float t = x - f0;                                  // exact
    f1 = __bfloat162float(__float2bfloat16_rn(t));
    r = t - f1;                                        // exact
}
__device__ __forceinline__ void mma_bf16(float d[4], const unsigned a[4],
                                         unsigned b0, unsigned b1) {
    asm("mma.sync.aligned.m16n8k16.row.col.f32.bf16.bf16.f32 "
        "{%0,%1,%2,%3}, {%4,%5,%6,%7}, {%8,%9}, {%0,%1,%2,%3};"
        : "+f"(d[0]), "+f"(d[1]), "+f"(d[2]), "+f"(d[3])
        : "r"(a[0]), "r"(a[1]), "r"(a[2]), "r"(a[3]), "r"(b0), "r"(b1));
}
__device__ __forceinline__ void cp_async16(unsigned smem_addr, const void* g) {
    asm volatile("cp.async.cg.shared.global [%0], [%1], 16;"
                 :: "r"(smem_addr), "l"(g));
}

// ---------------- prep: norms, split-norm maxima, counter reset ----------------
__global__ void cnorm_kernel(const float* __restrict__ centers) {
    int n = blockIdx.x * blockDim.x + threadIdx.x;
    if (n == 0) g_flagcnt = 0;           // reset per replay (before pass 1)
    if (n < KCENT) {
        const float4* c = reinterpret_cast<const float4*>(
            centers + (size_t)n * DIMK);
        float s0 = 0.f, s1 = 0.f, s2 = 0.f, s3 = 0.f;
        float sh1 = 0.f, sr = 0.f;
        #pragma unroll
        for (int k = 0; k < DIMK / 4; k++) {
            float4 v = __ldg(c + k);
            s0 = fmaf(v.x, v.x, s0);
            s1 = fmaf(v.y, v.y, s1);
            s2 = fmaf(v.z, v.z, s2);
            s3 = fmaf(v.w, v.w, s3);
            float e[4] = {v.x, v.y, v.z, v.w};
            #pragma unroll
            for (int j = 0; j < 4; j++) {
                float f0, f1, r;
                split2(e[j], f0, f1, r);
                sh1 = fmaf(f1, f1, sh1);
                sr  = fmaf(r, r, sr);
            }
        }
        float sc = (s0 + s1) + (s2 + s3);
        g_cnorm[n] = sc;
        atomicMax(&g_cmax_bits,   __float_as_int(sqrtf(sc) * 1.0002f));
        atomicMax(&g_ch1max_bits, __float_as_int(sqrtf(sh1) * 1.0002f));
        atomicMax(&g_crmax_bits,  __float_as_int(sqrtf(sr) * 1.0002f));
    }
}

// Build fragment-ordered bf16 h0/h1 blob from centers.
__global__ void csplit_kernel(const float* __restrict__ centers) {
    int id = blockIdx.x * blockDim.x + threadIdx.x;   // 128*4*32 = 16384
    if (id >= NTILES * 4 * 32) return;
    int lane = id & 31;
    int q    = (id >> 5) & 3;
    int t    = id >> 7;
    int n  = t * 8 + (lane >> 2);
    int kb = q * 16 + 2 * (lane & 3);
    const float* cr = centers + (size_t)n * DIMK;
    float f0a, f1a, ra, f0b, f1b, rb, f0c, f1c, rc, f0d, f1d, rd;
    split2(__ldg(cr + kb),     f0a, f1a, ra);
    split2(__ldg(cr + kb + 1), f0b, f1b, rb);
    split2(__ldg(cr + kb + 8), f0c, f1c, rc);
    split2(__ldg(cr + kb + 9), f0d, f1d, rd);
    uint4 b;
    b.x = pack_bf16(f0a, f0b);
    b.y = pack_bf16(f0c, f0d);
    b.z = pack_bf16(f1a, f1b);
    b.w = pack_bf16(f1c, f1d);
    g_bfrag[(t * 4 + q) * 32 + lane] = b;
}

// ---------------- pass 1: bf16x2 3-product GEMM + two-smallest + flag ----------------
__global__ void __launch_bounds__(THREADS)
label_mma_kernel(const float* __restrict__ inpt, float* __restrict__ out) {
    extern __shared__ __align__(16) unsigned char sm[];
    const unsigned sbase = (unsigned)__cvta_generic_to_shared(sm);
    float* cn_s = reinterpret_cast<float*>(sm + CN_OFF);

    const int tid  = threadIdx.x;
    const int wid  = tid >> 5;
    const int lane = tid & 31;
    const int r    = lane >> 2;   // 0..7
    const int cc   = lane & 3;    // 0..3
    const int m0   = blockIdx.x * BM;
    const int mrow = m0 + wid * 16;

    // Prefetch chunk 0 (linear copy: blob layout == smem layout)
    {
        const unsigned char* src = (const unsigned char*)g_bfrag;
        #pragma unroll
        for (int j = 0; j < CHUNK_BYTES / (THREADS * 16); j++)
            cp_async16(sbase + tid * 16 + j * (THREADS * 16),
                       src + tid * 16 + j * (THREADS * 16));
        asm volatile("cp.async.commit_group;");
    }

    // Center norms -> smem
    for (int i = tid; i < KCENT; i += THREADS) cn_s[i] = g_cnorm[i];

    // A fragments (h0, h1) + per-row norm partials (a, h1, resid)
    unsigned ah0[4][4], ah1[4][4];
    float sa0 = 0.f, sh10 = 0.f, sr0 = 0.f;
    float sa1 = 0.f, sh11 = 0.f, sr1 = 0.f;
    {
        const float* row0 = inpt + (size_t)(mrow + r) * INROW + DIMK;
        const float* row8 = inpt + (size_t)(mrow + r + 8) * INROW + DIMK;
        #pragma unroll
        for (int q = 0; q < 4; q++) {
            const int kb = q * 16 + 2 * cc;
            float f0[8], f1[8], rr[8];
            float xv[8];
            xv[0] = __ldg(row0 + kb);     xv[1] = __ldg(row0 + kb + 1);
            xv[2] = __ldg(row8 + kb);     xv[3] = __ldg(row8 + kb + 1);
            xv[4] = __ldg(row0 + kb + 8); xv[5] = __ldg(row0 + kb + 9);
            xv[6] = __ldg(row8 + kb + 8); xv[7] = __ldg(row8 + kb + 9);
            #pragma unroll
            for (int e = 0; e < 8; e++) split2(xv[e], f0[e], f1[e], rr[e]);
            ah0[q][0] = pack_bf16(f0[0], f0[1]);
            ah0[q][1] = pack_bf16(f0[2], f0[3]);
            ah0[q][2] = pack_bf16(f0[4], f0[5]);
            ah0[q][3] = pack_bf16(f0[6], f0[7]);
            ah1[q][0] = pack_bf16(f1[0], f1[1]);
            ah1[q][1] = pack_bf16(f1[2], f1[3]);
            ah1[q][2] = pack_bf16(f1[4], f1[5]);
            ah1[q][3] = pack_bf16(f1[6], f1[7]);
            #pragma unroll
            for (int e = 0; e < 8; e++) {
                // rows: e in {0,1,4,5} -> row r; {2,3,6,7} -> row r+8
                bool isr0 = ((e & 2) == 0);
                float xa = xv[e] * xv[e];
                float xh = f1[e] * f1[e];
                float xr = rr[e] * rr[e];
                if (isr0) { sa0 += xa; sh10 += xh; sr0 += xr; }
                else      { sa1 += xa; sh11 += xh; sr1 += xr; }
            }
        }
        #pragma unroll
        for (int off = 1; off <= 2; off <<= 1) {
            sa0  += __shfl_xor_sync(0xffffffffu, sa0, off);
            sh10 += __shfl_xor_sync(0xffffffffu, sh10, off);
            sr0  += __shfl_xor_sync(0xffffffffu, sr0, off);
            sa1  += __shfl_xor_sync(0xffffffffu, sa1, off);
            sh11 += __shfl_xor_sync(0xffffffffu, sh11, off);
            sr1  += __shfl_xor_sync(0xffffffffu, sr1, off);
        }
    }

    const float INF = __int_as_float(0x7f800000);
    float bd0 = INF, b2d0 = INF, bd1 = INF, b2d1 = INF;
    int   bn0 = 0, bn1 = 0;

    #pragma unroll 1
    for (int c = 0; c < NCHUNK; c++) {
        asm volatile("cp.async.wait_group 0;" ::: "memory");
        __syncthreads();

        if (c + 1 < NCHUNK) {
            const unsigned char* src =
                (const unsigned char*)g_bfrag + (size_t)(c + 1) * CHUNK_BYTES;
            unsigned dst = sbase + ((c + 1) & 1) * CHUNK_BYTES;
            #pragma unroll
            for (int j = 0; j < CHUNK_BYTES / (THREADS * 16); j++)
                cp_async16(dst + tid * 16 + j * (THREADS * 16),
                           src + tid * 16 + j * (THREADS * 16));
            asm volatile("cp.async.commit_group;");
        }

        const unsigned buf = sbase + (c & 1) * CHUNK_BYTES + lane * 16;

        #pragma unroll
        for (int t8 = 0; t8 < TPC; t8 += 2) {    // 2 tiles in flight
            float dA0[4] = {0.f, 0.f, 0.f, 0.f};  // h0*h0
            float dAx[4] = {0.f, 0.f, 0.f, 0.f};  // h0*h1 + h1*h0
            float dB0[4] = {0.f, 0.f, 0.f, 0.f};
            float dBx[4] = {0.f, 0.f, 0.f, 0.f};
            #pragma unroll
            for (int q = 0; q < 4; q++) {
                uint4 ba, bb;
                asm volatile("ld.shared.v4.b32 {%0,%1,%2,%3}, [%4];"
                             : "=r"(ba.x), "=r"(ba.y), "=r"(ba.z), "=r"(ba.w)
                             : "r"(buf + (((t8 + 0) * 4 + q) * 32) * 16));
                asm volatile("ld.shared.v4.b32 {%0,%1,%2,%3}, [%4];"
                             : "=r"(bb.x), "=r"(bb.y), "=r"(bb.z), "=r"(bb.w)
                             : "r"(buf + (((t8 + 1) * 4 + q) * 32) * 16));
                mma_bf16(dA0, ah0[q], ba.x, ba.y);
                mma_bf16(dAx, ah0[q], ba.z, ba.w);
                mma_bf16(dAx, ah1[q], ba.x, ba.y);
                mma_bf16(dB0, ah0[q], bb.x, bb.y);
                mma_bf16(dBx, ah0[q], bb.z, bb.w);
                mma_bf16(dBx, ah1[q], bb.x, bb.y);
            }
            #pragma unroll
            for (int p = 0; p < 2; p++) {
                const float* d0 = p ? dB0 : dA0;
                const float* dx = p ? dBx : dAx;
                const int nbase = c * 64 + (t8 + p) * 8 + 2 * cc;
                float2 cn = *reinterpret_cast<const float2*>(cn_s + nbase);
                float e0 = fmaf(-2.f, d0[0] + dx[0], cn.x);
                float e1 = fmaf(-2.f, d0[1] + dx[1], cn.y);
                float e2 = fmaf(-2.f, d0[2] + dx[2], cn.x);
                float e3 = fmaf(-2.f, d0[3] + dx[3], cn.y);
                if (e0 < bd0) { b2d0 = bd0; bd0 = e0; bn0 = nbase; }
                else if (e0 < b2d0) b2d0 = e0;
                if (e1 < bd0) { b2d0 = bd0; bd0 = e1; bn0 = nbase + 1; }
                else if (e1 < b2d0) b2d0 = e1;
                if (e2 < bd1) { b2d1 = bd1; bd1 = e2; bn1 = nbase; }
                else if (e2 < b2d1) b2d1 = e2;
                if (e3 < bd1) { b2d1 = bd1; bd1 = e3; bn1 = nbase + 1; }
                else if (e3 < b2d1) b2d1 = e3;
            }
        }
    }

    // Merge (min, min2) across the 4 cc-lanes (disjoint n-sets)
    #pragma unroll
    for (int off = 1; off <= 2; off <<= 1) {
        float od0 = __shfl_xor_sync(0xffffffffu, bd0, off);
        float o2d0 = __shfl_xor_sync(0xffffffffu, b2d0, off);
        int   on0 = __shfl_xor_sync(0xffffffffu, bn0, off);
        float od1 = __shfl_xor_sync(0xffffffffu, bd1, off);
        float o2d1 = __shfl_xor_sync(0xffffffffu, b2d1, off);
        int   on1 = __shfl_xor_sync(0xffffffffu, bn1, off);
        if (od0 < bd0 || (od0 == bd0 && on0 < bn0)) {
            b2d0 = fminf(bd0, o2d0); bd0 = od0; bn0 = on0;
        } else b2d0 = fminf(b2d0, od0);
        if (od1 < bd1 || (od1 == bd1 && on1 < bn1)) {
            b2d1 = fminf(bd1, o2d1); bd1 = od1; bn1 = on1;
        } else b2d1 = fminf(b2d1, od1);
    }

    if (cc == 0) {
        const float CM  = __int_as_float(g_cmax_bits);
        const float CH1 = __int_as_float(g_ch1max_bits);
        const float CR  = __int_as_float(g_crmax_bits);
        float na0 = sqrtf(sa0), nh0 = sqrtf(sh10), nr0 = sqrtf(sr0);
        float na1 = sqrtf(sa1), nh1 = sqrtf(sh11), nr1 = sqrtf(sr1);
        // |dot err| <= ||x_h1||*||c_h1|| + ||x_r||*(||c||+||c_r||)
        //            + ||x||*||c_r|| + accumulation
        float err0 = nh0 * CH1 + nr0 * (CM + CR) + na0 * CR + 5e-6f * na0 * CM;
        float err1 = nh1 * CH1 + nr1 * (CM + CR) + na1 * CR + 5e-6f * na1 * CM;
        float eps0 = 2.f * err0 + 1e-4f;
        float eps1 = 2.f * err1 + 1e-4f;
        out[mrow + r] = (float)bn0;
        out[mrow + r + 8] = (float)bn1;
        if (b2d0 - bd0 <= 2.f * eps0) {
            int i = atomicAdd(&g_flagcnt, 1);
            g_flaglist[i] = mrow + r;
        }
        if (b2d1 - bd1 <= 2.f * eps1) {
            int i = atomicAdd(&g_flagcnt, 1);
            g_flaglist[i] = mrow + r + 8;
        }
    }
}

// ---------------- pass 2: exact fp32 rescan for flagged points ----------------
// One warp per flagged point; lane l covers centers [l*32, l*32+32), ascending,
// two centers in flight for MLP.
__global__ void __launch_bounds__(256)
exact_pass_kernel(const float* __restrict__ inpt,
                  const float* __restrict__ centers,
                  float* __restrict__ out) {
    const int lane = threadIdx.x & 31;
    const int gw   = (blockIdx.x * blockDim.x + threadIdx.x) >> 5;
    const int nw   = (gridDim.x * blockDim.x) >> 5;
    const int cnt  = g_flagcnt;

    for (int i = gw; i < cnt; i += nw) {
        const int m = g_flaglist[i];
        const float4* xr = reinterpret_cast<const float4*>(
            inpt + (size_t)m * INROW + DIMK);
        float4 xv[16];
        #pragma unroll
        for (int j = 0; j < 16; j++) xv[j] = __ldg(xr + j);

        float bm = __int_as_float(0x7f800000);
        int   bn = 0;
        const int nbase = lane * 32;
        #pragma unroll 1
        for (int c = 0; c < 32; c += 2) {
            const float4* cr0 = reinterpret_cast<const float4*>(
                centers + (size_t)(nbase + c) * DIMK);
            const float4* cr1 = reinterpret_cast<const float4*>(
                centers + (size_t)(nbase + c + 1) * DIMK);
            float s0 = 0.f, s1 = 0.f;
            #pragma unroll
            for (int j = 0; j < 16; j++) {
                float4 c0 = __ldg(cr0 + j);
                float4 c1 = __ldg(cr1 + j);
                s0 = fmaf(xv[j].x, c0.x, s0);
                s0 = fmaf(xv[j].y, c0.y, s0);
                s0 = fmaf(xv[j].z, c0.z, s0);
                s0 = fmaf(xv[j].w, c0.w, s0);
                s1 = fmaf(xv[j].x, c1.x, s1);
                s1 = fmaf(xv[j].y, c1.y, s1);
                s1 = fmaf(xv[j].z, c1.z, s1);
                s1 = fmaf(xv[j].w, c1.w, s1);
            }
            float d0 = fmaf(-2.f, s0, g_cnorm[nbase + c]);
            float d1 = fmaf(-2.f, s1, g_cnorm[nbase + c + 1]);
            if (d0 < bm) { bm = d0; bn = nbase + c; }      // ascending order
            if (d1 < bm) { bm = d1; bn = nbase + c + 1; }
        }
        #pragma unroll
        for (int off = 16; off > 0; off >>= 1) {
            float od = __shfl_down_sync(0xffffffffu, bm, off);
            int   on = __shfl_down_sync(0xffffffffu, bn, off);
            if (od < bm || (od == bm && on < bn)) { bm = od; bn = on; }
        }
        if (lane == 0) out[m] = (float)bn;
    }
}

extern "C" void kernel_launch(void* const* d_in, const int* in_sizes, int n_in,
                              void* d_out, int out_size) {
    // Identify inputs by element count:
    //   inpt: 16777216 elements (unique); centers1: second 65536-elem tensor
    const float* inpt     = nullptr;
    const float* centers1 = nullptr;
    int centers_seen = 0;
    for (int i = 0; i < n_in; i++) {
        if (in_sizes[i] == NPTS * INROW) {
            inpt = (const float*)d_in[i];
        } else if (in_sizes[i] == KCENT * DIMK) {
            centers_seen++;
            if (centers_seen == 2) centers1 = (const float*)d_in[i];
        }
    }
    if (!inpt)     inpt     = (const float*)d_in[0];
    if (!centers1) centers1 = (const float*)d_in[n_in - 1];

    float* out = (float*)d_out;

    cudaFuncSetAttribute(label_mma_kernel,
                         cudaFuncAttributeMaxDynamicSharedMemorySize, SMEM_REQ);

    cnorm_kernel<<<(KCENT + 255) / 256, 256>>>(centers1);
    csplit_kernel<<<(NTILES * 4 * 32 + 255) / 256, 256>>>(centers1);
    label_mma_kernel<<<NPTS / BM, THREADS, SMEM_REQ>>>(inpt, out);
    exact_pass_kernel<<<1024, 256>>>(inpt, centers1, out);
}